// round 2
// baseline (speedup 1.0000x reference)
#include <cuda_runtime.h>
#include <cstdint>
#include <cstddef>

#define BB 8
#define NN 2048
#define DD 128

// Scratch (allocation-free rule: __device__ globals)
__device__ float g_z[BB * NN * DD];
__device__ float g_x[BB * NN * DD];
__device__ float g_invden[BB * NN];

typedef unsigned long long u64;

__device__ __forceinline__ void fma2(u64 &c, u64 a, u64 b) {
    // packed fp32x2 FMA — 2 fp32 FMA per issue on sm_103a
    asm("fma.rn.f32x2 %0, %1, %2, %0;" : "+l"(c) : "l"(a), "l"(b));
}
__device__ __forceinline__ float2 unpack2(u64 v) {
    float2 r; asm("mov.b64 {%0, %1}, %2;" : "=f"(r.x), "=f"(r.y) : "l"(v)); return r;
}

// Unified tiled GEMM, CTA tile 128x128, 256 threads, BK=8, smem ping-pong.
//   zk path : Z = X @ W          (KTOT=128, no EPI)
//   AX path : out = relu((A @ Z + bias) * invden)   (KTOT=2048, EPI)
//             FIRST also computes invden = 1/(rowsum(A)+1) locally (free).
// Mainloop has ZERO packing MOVs: A pairs come straight from ulonglong2 LDS of
// transposed-A smem; B operands come pre-DUPLICATED from a granule-permuted
// two-plane smem layout, so each 16B LDS yields two ready f32x2 operands.
template<int KTOT, bool FIRST, bool EPI>
__global__ __launch_bounds__(256, 1) void gemm_k(
    const float* __restrict__ Aptr, size_t sA, int lda,
    const float* __restrict__ Bptr, size_t sB,
    const float* __restrict__ bias,
    const float* __restrict__ invden_g,
    float* __restrict__ invden_out,
    float* __restrict__ Outp, size_t sOut)
{
    __shared__ __align__(16) float As[2][8][132];   // [buf][k][m] transposed, pad->conflict-free STS
    __shared__ __align__(16) float Bd[2][8][256];   // [buf][k][dup-plane layout]
    __shared__ float sm_inv[128];

    const int tid = threadIdx.x;
    const int m0  = blockIdx.x * 128;
    const float* Ab = Aptr + (size_t)blockIdx.y * sA;
    const float* Bb = Bptr + (size_t)blockIdx.y * sB;
    float*       Ob = Outp + (size_t)blockIdx.y * sOut;

    // loaders: one float4 per thread per 8-deep K-tile
    const int mA = tid >> 1, kA = (tid & 1) * 4;        // A: 128 rows x 8 k
    const int kB = tid >> 5, nB = (tid & 31) * 4;       // B: 8 k x 128 n
    // compute mapping
    const int tx = tid & 15, ty = tid >> 4;
    const int r0 = ty * 4, r1 = r0 + 64;
    const int c0 = tx * 4, c1 = c0 + 64;

    const float* aP = Ab + (size_t)(m0 + mA) * lda + kA;
    const float* bP = Bb + (size_t)kB * DD + nB;

    u64 acc[4][8];
    #pragma unroll
    for (int i = 0; i < 4; i++)
        #pragma unroll
        for (int j = 0; j < 8; j++) acc[i][j] = 0ull;

    float rs = 0.f;

    float4 pa = *(const float4*)aP;  aP += 8;
    float4 pb = *(const float4*)bP;  bP += 8 * DD;

    // ---- helpers ----
    auto sts = [&](float (*Asb)[132], float (*Bdb)[256]) {
        // A transposed scalar stores (conflict-free with pad 132)
        Asb[kA + 0][mA] = pa.x;
        Asb[kA + 1][mA] = pa.y;
        Asb[kA + 2][mA] = pa.z;
        Asb[kA + 3][mA] = pa.w;
        // B duplicated, granule-permuted: logical granule g (cols 2g,2g+1)
        // lives at physical granule ((g&1)<<5)|(g>>1).
        float4 lo = make_float4(pb.x, pb.x, pb.y, pb.y);
        float4 hi = make_float4(pb.z, pb.z, pb.w, pb.w);
        *(float4*)&Bdb[kB][nB]       = lo;   // even granules -> plane words [0,128)
        *(float4*)&Bdb[kB][128 + nB] = hi;   // odd  granules -> plane words [128,256)
    };
    auto comp = [&](const float (*Asb)[132], const float (*Bdb)[256]) {
        #pragma unroll
        for (int k = 0; k < 8; k++) {
            ulonglong2 aA = *(const ulonglong2*)&Asb[k][r0];       // pairs (r0,r0+1),(r0+2,r0+3)
            ulonglong2 aB = *(const ulonglong2*)&Asb[k][r1];
            ulonglong2 b0 = *(const ulonglong2*)&Bdb[k][4 * tx];        // dup c0, c0+1
            ulonglong2 b1 = *(const ulonglong2*)&Bdb[k][128 + 4 * tx];  // dup c0+2, c0+3
            ulonglong2 b2 = *(const ulonglong2*)&Bdb[k][64 + 4 * tx];   // dup c1, c1+1
            ulonglong2 b3 = *(const ulonglong2*)&Bdb[k][192 + 4 * tx];  // dup c1+2, c1+3
            u64 ap[4] = {aA.x, aA.y, aB.x, aB.y};
            u64 bp[8] = {b0.x, b0.y, b1.x, b1.y, b2.x, b2.y, b3.x, b3.y};
            #pragma unroll
            for (int i = 0; i < 4; i++)
                #pragma unroll
                for (int j = 0; j < 8; j++)
                    fma2(acc[i][j], ap[i], bp[j]);
        }
    };

    // ---- mainloop: ping-pong, one sync per tile ----
    sts(As[0], Bd[0]);
    if (FIRST) rs += pa.x + pa.y + pa.z + pa.w;
    __syncthreads();

    float (*Ac)[132] = As[0]; float (*Bc)[256] = Bd[0];
    float (*An)[132] = As[1]; float (*Bn)[256] = Bd[1];

    constexpr int NT = KTOT / 8;
    #pragma unroll 1
    for (int t = 0; t < NT - 1; t++) {
        pa = *(const float4*)aP;  aP += 8;
        pb = *(const float4*)bP;  bP += 8 * DD;
        comp(Ac, Bc);
        if (FIRST) rs += pa.x + pa.y + pa.z + pa.w;
        sts(An, Bn);
        __syncthreads();
        { float (*t1)[132] = Ac; Ac = An; An = t1; }
        { float (*t2)[256] = Bc; Bc = Bn; Bn = t2; }
    }
    comp(Ac, Bc);

    // ---- denom (layer 0): full rowsum lives inside this CTA ----
    if (FIRST) {
        float s = rs + __shfl_xor_sync(0xffffffffu, rs, 1);  // partner tid^1 shares row mA
        float inv = 1.0f / (s + 1.0f);
        if ((tid & 1) == 0) {
            sm_inv[mA] = inv;
            invden_out[(size_t)blockIdx.y * NN + m0 + mA] = inv;
        }
        __syncthreads();
    }

    // ---- epilogue ----
    float4 bi0, bi1;
    if (EPI) {
        bi0 = *(const float4*)(bias + c0);
        bi1 = *(const float4*)(bias + c1);
    }
    const int rowbase[4] = {r0, r0 + 2, r1, r1 + 2};
    #pragma unroll
    for (int i = 0; i < 4; i++) {
        float2 u[8];
        #pragma unroll
        for (int j = 0; j < 8; j++) u[j] = unpack2(acc[i][j]);
        #pragma unroll
        for (int h = 0; h < 2; h++) {
            const int r = rowbase[i] + h;
            float v0 = h ? u[0].y : u[0].x;
            float v1 = h ? u[1].y : u[1].x;
            float v2 = h ? u[2].y : u[2].x;
            float v3 = h ? u[3].y : u[3].x;
            float v4 = h ? u[4].y : u[4].x;
            float v5 = h ? u[5].y : u[5].x;
            float v6 = h ? u[6].y : u[6].x;
            float v7 = h ? u[7].y : u[7].x;
            float* orow = Ob + (size_t)(m0 + r) * DD;
            if (EPI) {
                const float id = FIRST ? sm_inv[r]
                                       : invden_g[(size_t)blockIdx.y * NN + m0 + r];
                float4 o0, o1;
                o0.x = fmaxf((v0 + bi0.x) * id, 0.f);
                o0.y = fmaxf((v1 + bi0.y) * id, 0.f);
                o0.z = fmaxf((v2 + bi0.z) * id, 0.f);
                o0.w = fmaxf((v3 + bi0.w) * id, 0.f);
                o1.x = fmaxf((v4 + bi1.x) * id, 0.f);
                o1.y = fmaxf((v5 + bi1.y) * id, 0.f);
                o1.z = fmaxf((v6 + bi1.z) * id, 0.f);
                o1.w = fmaxf((v7 + bi1.w) * id, 0.f);
                *(float4*)(orow + c0) = o0;
                *(float4*)(orow + c1) = o1;
            } else {
                float4 o0 = {v0, v1, v2, v3};
                float4 o1 = {v4, v5, v6, v7};
                *(float4*)(orow + c0) = o0;
                *(float4*)(orow + c1) = o1;
            }
        }
    }
}

extern "C" void kernel_launch(void* const* d_in, const int* in_sizes, int n_in,
                              void* d_out, int out_size)
{
    // Identify inputs by element count (all distinct)
    const float *inputs = nullptr, *adj = nullptr, *W = nullptr, *bias = nullptr;
    for (int i = 0; i < n_in; i++) {
        const long long s = in_sizes[i];
        if      (s == (long long)BB * NN * DD) inputs = (const float*)d_in[i];
        else if (s == (long long)BB * NN * NN) adj    = (const float*)d_in[i];
        else if (s == 3LL * DD * DD)           W      = (const float*)d_in[i];
        else if (s == 3LL * DD)                bias   = (const float*)d_in[i];
    }
    float* out = (float*)d_out;

    float *z, *x, *invd;
    cudaGetSymbolAddress((void**)&z,    g_z);
    cudaGetSymbolAddress((void**)&x,    g_x);
    cudaGetSymbolAddress((void**)&invd, g_invden);

    const dim3 blk(256);
    const dim3 gAX(NN / 128, BB);          // A@Z per batch
    const dim3 gZK((BB * NN) / 128, 1);    // X@W flat over all rows
    const size_t sAdj = (size_t)NN * NN;
    const size_t sX   = (size_t)NN * DD;

    // layer 0:  Z = X@W0 ; X1 = relu((A@Z + b0)*invden)  [invden computed in-pass]
    gemm_k<DD, false, false><<<gZK, blk>>>(inputs, 0, DD, W, 0,
                                           nullptr, nullptr, nullptr, z, 0);
    gemm_k<NN, true,  true ><<<gAX, blk>>>(adj, sAdj, NN, z, sX,
                                           bias, nullptr, invd, x, sX);
    // layer 1
    gemm_k<DD, false, false><<<gZK, blk>>>(x, 0, DD, W + DD * DD, 0,
                                           nullptr, nullptr, nullptr, z, 0);
    gemm_k<NN, false, true ><<<gAX, blk>>>(adj, sAdj, NN, z, sX,
                                           bias + DD, invd, nullptr, x, sX);
    // layer 2
    gemm_k<DD, false, false><<<gZK, blk>>>(x, 0, DD, W + 2 * DD * DD, 0,
                                           nullptr, nullptr, nullptr, z, 0);
    gemm_k<NN, false, true ><<<gAX, blk>>>(adj, sAdj, NN, z, sX,
                                           bias + 2 * DD, invd, nullptr, out, sX);
}

// round 4
// speedup vs baseline: 1.9895x; 1.9895x over previous
#include <cuda_runtime.h>
#include <cstdint>
#include <cstddef>

#define BB 8
#define NN 2048
#define DD 128

// ---------------- scratch (no allocs allowed) ----------------
__device__ float g_zt[BB * DD * NN];    // Z^T  [b][feature n][token k], tf32-in-f32 bits
__device__ float g_x [BB * NN * DD];    // layer activations [b][token][feat]
__device__ float g_invden[BB * NN];

typedef unsigned long long u64;

// ---------------- small PTX helpers ----------------
__device__ __forceinline__ uint32_t smem_u32(const void* p) {
    uint32_t a;
    asm("{ .reg .u64 t; cvta.to.shared.u64 t, %1; cvt.u32.u64 %0, t; }" : "=r"(a) : "l"(p));
    return a;
}
__device__ __forceinline__ void cp16(uint32_t dst, const void* src) {
    asm volatile("cp.async.cg.shared.global [%0], [%1], 16;" :: "r"(dst), "l"(src));
}
__device__ __forceinline__ void cp_commit() {
    asm volatile("cp.async.commit_group;" ::: "memory");
}
__device__ __forceinline__ uint32_t cvt_tf32(float x) {
    uint32_t r; asm("cvt.rna.tf32.f32 %0, %1;" : "=r"(r) : "f"(x)); return r;
}
// m16n8k8 tf32 HMMA, fp32 accumulate (sm_80+ path, no 'a' target needed)
__device__ __forceinline__ void mma_tf32(float* d,
    uint32_t a0, uint32_t a1, uint32_t a2, uint32_t a3,
    uint32_t b0, uint32_t b1)
{
    asm volatile(
        "mma.sync.aligned.m16n8k8.row.col.f32.tf32.tf32.f32 "
        "{%0,%1,%2,%3}, {%4,%5,%6,%7}, {%8,%9}, {%0,%1,%2,%3};"
        : "+f"(d[0]), "+f"(d[1]), "+f"(d[2]), "+f"(d[3])
        : "r"(a0), "r"(a1), "r"(a2), "r"(a3), "r"(b0), "r"(b1));
}

// f32x2 helpers (zk kernel)
__device__ __forceinline__ void fma2(u64 &c, u64 a, u64 b) {
    asm("fma.rn.f32x2 %0, %1, %2, %0;" : "+l"(c) : "l"(a), "l"(b));
}
__device__ __forceinline__ float2 unpack2(u64 v) {
    float2 r; asm("mov.b64 {%0, %1}, %2;" : "=f"(r.x), "=f"(r.y) : "l"(v)); return r;
}

// =================================================================
//  AX kernel (tf32 HMMA): out = relu((A @ Z + bias) * invden)
//  A fp32 streamed raw (tf32 = f32 bits, cvt.rna on fragments).
//  Z pre-rounded tf32, transposed [b][n][token].
//  CTA 128(M) x 128(N), 8 warps (warp tile 32x64), BK=32, 3-stage cp.async.
// =================================================================
#define AXPADW 36                    // floats per padded 32-k row (144 B)
#define AX_ROWB (AXPADW * 4)         // 144
#define AX_TILEB (128 * AX_ROWB)     // 18432 per operand per stage
#define AX_STAGE (2 * AX_TILEB)      // 36864
#define AX_SMEM (1024 + 3 * AX_STAGE)

template<bool FIRST>
__global__ __launch_bounds__(256, 1) void ax_hmma(
    const float* __restrict__ A,
    const float* __restrict__ Zt,
    const float* __restrict__ bias,
    const float* __restrict__ invden_g,
    float* __restrict__ invden_out,
    float* __restrict__ Out)
{
    extern __shared__ __align__(16) char sm[];
    float* sb   = reinterpret_cast<float*>(sm);        // bias [128]
    float* sinv = sb + 128;                            // invden [128]
    const uint32_t smb = smem_u32(sm);

    const int tid = threadIdx.x, lane = tid & 31, wid = tid >> 5;
    const int b = blockIdx.y, m0 = blockIdx.x * 128;

    if (tid < 128) {
        sb[tid] = bias[tid];
        if (!FIRST) sinv[tid] = invden_g[(size_t)b * NN + m0 + tid];
    }
    __syncthreads();

    // loader mapping: 256 threads cover 128 rows x 32 k (2 thr/row, 16 k each)
    const int lrow = tid >> 1, lhalf = tid & 1;
    const float* agl = A  + ((size_t)b * NN + m0 + lrow) * NN + lhalf * 16;
    const float* zgl = Zt + ((size_t)b * DD + lrow)      * NN + lhalf * 16;
    const uint32_t dst_off = (uint32_t)(lrow * AX_ROWB + lhalf * 64);

    auto load_chunk = [&](int i) {
        const int s = i % 3;
        const int k0 = i * 32;
        const uint32_t da = smb + 1024 + s * AX_STAGE + dst_off;
        const uint32_t dz = da + AX_TILEB;
        const float* sa = agl + k0;
        const float* sz = zgl + k0;
        cp16(da,      sa);      cp16(da + 16, sa + 4);
        cp16(da + 32, sa + 8);  cp16(da + 48, sa + 12);
        cp16(dz,      sz);      cp16(dz + 16, sz + 4);
        cp16(dz + 32, sz + 8);  cp16(dz + 48, sz + 12);
        cp_commit();
    };

    // compute mapping
    const int g = lane >> 2, c = lane & 3;
    const int wm = (wid & 3) * 32, wn = (wid >> 2) * 64;
    const int rA0 = wm + g;          // m16 tile 0 rows rA0, rA0+8
    const int rA1 = wm + 16 + g;     // m16 tile 1

    float acc[2][8][4];
    #pragma unroll
    for (int mi = 0; mi < 2; mi++)
        #pragma unroll
        for (int nj = 0; nj < 8; nj++)
            #pragma unroll
            for (int q = 0; q < 4; q++) acc[mi][nj][q] = 0.f;

    float rs = 0.f;

    load_chunk(0);
    load_chunk(1);

    #pragma unroll 1
    for (int i = 0; i < 64; i++) {
        if (i < 62) { asm volatile("cp.async.wait_group 1;" ::: "memory"); }
        else        { asm volatile("cp.async.wait_group 0;" ::: "memory"); }
        __syncthreads();
        if (i < 62) load_chunk(i + 2);

        const int s = i % 3;
        const float* As = reinterpret_cast<const float*>(sm + 1024 + s * AX_STAGE);
        const float* Zs = As + AX_TILEB / 4;
        const uint32_t* Zu = reinterpret_cast<const uint32_t*>(Zs);

        if (FIRST) {  // rowsum of this A chunk from smem (layer-0 denom)
            const float4* ar = reinterpret_cast<const float4*>(
                As + lrow * AXPADW + lhalf * 16);
            float4 v0 = ar[0], v1 = ar[1], v2 = ar[2], v3 = ar[3];
            rs += (v0.x + v0.y + v0.z + v0.w) + (v1.x + v1.y + v1.z + v1.w)
                + (v2.x + v2.y + v2.z + v2.w) + (v3.x + v3.y + v3.z + v3.w);
        }

        #pragma unroll
        for (int ks = 0; ks < 4; ks++) {
            const int kk = ks * 8 + c;
            uint32_t a0[4], a1[4];
            a0[0] = cvt_tf32(As[rA0       * AXPADW + kk]);
            a0[1] = cvt_tf32(As[(rA0 + 8) * AXPADW + kk]);
            a0[2] = cvt_tf32(As[rA0       * AXPADW + kk + 4]);
            a0[3] = cvt_tf32(As[(rA0 + 8) * AXPADW + kk + 4]);
            a1[0] = cvt_tf32(As[rA1       * AXPADW + kk]);
            a1[1] = cvt_tf32(As[(rA1 + 8) * AXPADW + kk]);
            a1[2] = cvt_tf32(As[rA1       * AXPADW + kk + 4]);
            a1[3] = cvt_tf32(As[(rA1 + 8) * AXPADW + kk + 4]);
            #pragma unroll
            for (int nj = 0; nj < 8; nj++) {
                const int zr = (wn + 8 * nj + g) * AXPADW;
                uint32_t b0 = Zu[zr + kk];
                uint32_t b1 = Zu[zr + kk + 4];
                mma_tf32(acc[0][nj], a0[0], a0[1], a0[2], a0[3], b0, b1);
                mma_tf32(acc[1][nj], a1[0], a1[1], a1[2], a1[3], b0, b1);
            }
        }
    }

    if (FIRST) {
        float stot = rs + __shfl_xor_sync(0xffffffffu, rs, 1);
        float inv = 1.0f / (stot + 1.0f);
        if (lhalf == 0) {
            sinv[lrow] = inv;
            invden_out[(size_t)b * NN + m0 + lrow] = inv;
        }
        __syncthreads();
    }

    // ---- epilogue: bias + *invden + relu, float2 stores ----
    #pragma unroll
    for (int mi = 0; mi < 2; mi++) {
        const int r_lo = (mi ? rA1 : rA0);
        const int r_hi = r_lo + 8;
        const float inv_lo = sinv[r_lo];
        const float inv_hi = sinv[r_hi];
        float* o_lo = Out + ((size_t)b * NN + m0 + r_lo) * DD;
        float* o_hi = Out + ((size_t)b * NN + m0 + r_hi) * DD;
        #pragma unroll
        for (int nj = 0; nj < 8; nj++) {
            const int col = wn + 8 * nj + 2 * c;
            const float b0f = sb[col], b1f = sb[col + 1];
            float2 vlo, vhi;
            vlo.x = fmaxf((acc[mi][nj][0] + b0f) * inv_lo, 0.f);
            vlo.y = fmaxf((acc[mi][nj][1] + b1f) * inv_lo, 0.f);
            vhi.x = fmaxf((acc[mi][nj][2] + b0f) * inv_hi, 0.f);
            vhi.y = fmaxf((acc[mi][nj][3] + b1f) * inv_hi, 0.f);
            *reinterpret_cast<float2*>(o_lo + col) = vlo;
            *reinterpret_cast<float2*>(o_hi + col) = vhi;
        }
    }
}

// =================================================================
//  zk kernel (f32x2 SIMT): Z = X @ W, epilogue writes Z^T [b][n][t]
//  as RNA-rounded tf32 bits. Tile 64(tokens) x 128(feat), 256 CTAs.
// =================================================================
__global__ __launch_bounds__(256, 1) void zk64(
    const float* __restrict__ X, const float* __restrict__ W,
    float* __restrict__ Zt)
{
    __shared__ __align__(16) float As[2][8][68];    // [buf][k][token] transposed
    __shared__ __align__(16) float Bd[2][8][256];   // [buf][k][dup planes]

    const int tid = threadIdx.x;
    const int m0g = blockIdx.x * 64;
    const int b = m0g >> 11, t0 = m0g & 2047;

    const int tx = tid & 15, ty = tid >> 4;
    const int r = ty * 4, c0 = tx * 4;

    const int arow = tid >> 1, ahalf = tid & 1;     // A loader (tid<128)
    const int bk = tid >> 5, bn = (tid & 31) * 4;   // B loader (all)

    u64 acc[2][8];
    #pragma unroll
    for (int i = 0; i < 2; i++)
        #pragma unroll
        for (int j = 0; j < 8; j++) acc[i][j] = 0ull;

    float4 va, vb;
    auto ldg = [&](int k0) {
        if (tid < 128)
            va = *reinterpret_cast<const float4*>(
                X + (size_t)(m0g + arow) * DD + k0 + ahalf * 4);
        vb = *reinterpret_cast<const float4*>(
                W + (size_t)(k0 + bk) * DD + bn);
    };
    auto sts = [&](int s) {
        if (tid < 128) {
            As[s][ahalf * 4 + 0][arow] = va.x;
            As[s][ahalf * 4 + 1][arow] = va.y;
            As[s][ahalf * 4 + 2][arow] = va.z;
            As[s][ahalf * 4 + 3][arow] = va.w;
        }
        *reinterpret_cast<float4*>(&Bd[s][bk][bn])       = make_float4(vb.x, vb.x, vb.y, vb.y);
        *reinterpret_cast<float4*>(&Bd[s][bk][128 + bn]) = make_float4(vb.z, vb.z, vb.w, vb.w);
    };
    auto comp = [&](int s) {
        #pragma unroll
        for (int k = 0; k < 8; k++) {
            ulonglong2 aA = *reinterpret_cast<const ulonglong2*>(&As[s][k][r]);
            ulonglong2 p0 = *reinterpret_cast<const ulonglong2*>(&Bd[s][k][4 * tx]);
            ulonglong2 p1 = *reinterpret_cast<const ulonglong2*>(&Bd[s][k][128 + 4 * tx]);
            ulonglong2 p2 = *reinterpret_cast<const ulonglong2*>(&Bd[s][k][64 + 4 * tx]);
            ulonglong2 p3 = *reinterpret_cast<const ulonglong2*>(&Bd[s][k][192 + 4 * tx]);
            u64 bq[8] = {p0.x, p0.y, p1.x, p1.y, p2.x, p2.y, p3.x, p3.y};
            #pragma unroll
            for (int j = 0; j < 8; j++) {
                fma2(acc[0][j], aA.x, bq[j]);
                fma2(acc[1][j], aA.y, bq[j]);
            }
        }
    };

    ldg(0); sts(0);
    __syncthreads();
    #pragma unroll 1
    for (int t = 0; t < 16; t++) {
        if (t < 15) ldg((t + 1) * 8);
        comp(t & 1);
        if (t < 15) sts((t + 1) & 1);
        __syncthreads();
    }

    // epilogue: transposed tf32 writes, float4 per (col)
    #pragma unroll
    for (int j = 0; j < 8; j++) {
        const int col = (j < 4) ? (c0 + j) : (c0 + 64 + (j - 4));
        float2 u0 = unpack2(acc[0][j]);   // tokens r, r+1
        float2 u1 = unpack2(acc[1][j]);   // tokens r+2, r+3
        uint4 o;
        o.x = cvt_tf32(u0.x); o.y = cvt_tf32(u0.y);
        o.z = cvt_tf32(u1.x); o.w = cvt_tf32(u1.y);
        *reinterpret_cast<uint4*>(Zt + ((size_t)b * DD + col) * NN + t0 + r) = o;
    }
}

// =================================================================
extern "C" void kernel_launch(void* const* d_in, const int* in_sizes, int n_in,
                              void* d_out, int out_size)
{
    const float *inputs = nullptr, *adj = nullptr, *W = nullptr, *bias = nullptr;
    for (int i = 0; i < n_in; i++) {
        const long long s = in_sizes[i];
        if      (s == (long long)BB * NN * DD) inputs = (const float*)d_in[i];
        else if (s == (long long)BB * NN * NN) adj    = (const float*)d_in[i];
        else if (s == 3LL * DD * DD)           W      = (const float*)d_in[i];
        else if (s == 3LL * DD)                bias   = (const float*)d_in[i];
    }
    float* out = (float*)d_out;

    float *zt, *x, *invd;
    cudaGetSymbolAddress((void**)&zt,   g_zt);
    cudaGetSymbolAddress((void**)&x,    g_x);
    cudaGetSymbolAddress((void**)&invd, g_invden);

    static bool attr_done = false;
    if (!attr_done) {
        cudaFuncSetAttribute(ax_hmma<true>,  cudaFuncAttributeMaxDynamicSharedMemorySize, AX_SMEM);
        cudaFuncSetAttribute(ax_hmma<false>, cudaFuncAttributeMaxDynamicSharedMemorySize, AX_SMEM);
        attr_done = true;
    }

    const dim3 blk(256);
    const dim3 gAX(NN / 128, BB);             // 16 x 8 = 128 CTAs
    const dim3 gZK((BB * NN) / 64, 1);        // 256 CTAs

    // layer 0
    zk64<<<gZK, blk>>>(inputs, W, zt);
    ax_hmma<true><<<gAX, blk, AX_SMEM>>>(adj, zt, bias, nullptr, invd, x);
    // layer 1
    zk64<<<gZK, blk>>>(x, W + DD * DD, zt);
    ax_hmma<false><<<gAX, blk, AX_SMEM>>>(adj, zt, bias + DD, invd, nullptr, x);
    // layer 2
    zk64<<<gZK, blk>>>(x, W + 2 * DD * DD, zt);
    ax_hmma<false><<<gAX, blk, AX_SMEM>>>(adj, zt, bias + 2 * DD, invd, nullptr, out);
}